// round 2
// baseline (speedup 1.0000x reference)
#include <cuda_runtime.h>
#include <cstdint>

// ============================================================================
// FlaxLinear per-irrep (mul=512, irreps 0e+1e+2e) fused GEMM for sm_103 (base).
//
// out[b, off_l + w*d + i] = PW * sum_u w_l[u,w] * x[b, off_l + u*d + i]  (+b0)
//
// The harness compiles to base compute_103 (no 'a' features), so no tcgen05.
// Tensor cores via legacy mma.sync.m16n8k8 tf32 (sm_80+ generic PTX).
//
//  - prep kernel: Wt[l][w][u] = rna_tf32(PW * w_l[u][w])  (K-major B)
//  - main kernel: CTA tile 128 rows (rho=(b,i)) x 128 w-cols, K=512 in 16
//    chunks of 32, double-buffered smem (A: LDG+deinterleave STS, B: cp.async),
//    XOR-swizzled smem for conflict-free tf32 fragment LDS.
//  - epilogue: C regs -> padded smem -> coalesced deinterleaved stores (+bias).
// ============================================================================

#define MULC 512
#define DTOT 4608
#define PW   0.044194173824159216f   // 512^-0.5

__device__ float g_Wt[3 * MULC * MULC];

// ---------------- helpers ----------------
__device__ __forceinline__ uint32_t smem_u32(const void* p) {
    uint32_t a;
    asm("{ .reg .u64 t; cvta.to.shared.u64 t, %1; cvt.u32.u64 %0, t; }" : "=r"(a) : "l"(p));
    return a;
}

__device__ __forceinline__ uint32_t f2tf32(float f) {
    uint32_t u; asm("cvt.rna.tf32.f32 %0, %1;" : "=r"(u) : "f"(f)); return u;
}

__device__ __forceinline__ void mma_tf32(float* c, const uint32_t* a, const uint32_t* b) {
    asm volatile(
        "mma.sync.aligned.m16n8k8.row.col.f32.tf32.tf32.f32 "
        "{%0,%1,%2,%3},{%4,%5,%6,%7},{%8,%9},{%0,%1,%2,%3};"
        : "+f"(c[0]), "+f"(c[1]), "+f"(c[2]), "+f"(c[3])
        : "r"(a[0]), "r"(a[1]), "r"(a[2]), "r"(a[3]), "r"(b[0]), "r"(b[1]));
}

__device__ __forceinline__ void cp_async16(uint32_t dst, const void* src) {
    asm volatile("cp.async.cg.shared.global [%0], [%1], 16;" :: "r"(dst), "l"(src) : "memory");
}
__device__ __forceinline__ void cp_commit() {
    asm volatile("cp.async.commit_group;" ::: "memory");
}
template <int N>
__device__ __forceinline__ void cp_wait() {
    asm volatile("cp.async.wait_group %0;" :: "n"(N) : "memory");
}

// smem: stage s at s*32KB: As (128x32 fl, 16KB) then Bs (128x32 fl, 16KB).
// XOR swizzle within a 32-float row: col' = col ^ ((row&7)<<2)
static constexpr uint32_t STAGE_BYTES = 32768;
static constexpr uint32_t BS_OFF      = 16384;
static constexpr uint32_t CS_PITCH    = 132;                    // floats
static constexpr uint32_t SMEM_BYTES  = 2 * STAGE_BYTES + 4096; // >= 128*132*4=67584
static_assert(SMEM_BYTES >= 128 * CS_PITCH * 4, "Cs fits");

// ---------------- weight prep: Wt[l][w][u] = rna_tf32(PW * w[u][w]) ----------
__global__ void prep_w_kernel(const float* __restrict__ w0,
                              const float* __restrict__ w1,
                              const float* __restrict__ w2) {
    __shared__ float tile[32][33];
    const int l = blockIdx.z;
    const float* w = (l == 0) ? w0 : (l == 1) ? w1 : w2;
    float* wt = g_Wt + l * MULC * MULC;
    const int u0 = blockIdx.y * 32, c0 = blockIdx.x * 32;
    const int tx = threadIdx.x, ty = threadIdx.y;
    #pragma unroll
    for (int j = ty; j < 32; j += 8)
        tile[j][tx] = w[(u0 + j) * MULC + c0 + tx];
    __syncthreads();
    #pragma unroll
    for (int j = ty; j < 32; j += 8) {
        float v = PW * tile[tx][j];
        wt[(c0 + j) * MULC + u0 + tx] = __uint_as_float(f2tf32(v));
    }
}

// ---------------- stage loaders ----------------
template <int D, int OFF>
__device__ __forceinline__ void load_A(const float* __restrict__ x, float* As,
                                       int rho0, int k0, int b_lo, int nb) {
    const int a_v4 = nb * 8 * D;
    for (int v = threadIdx.x; v < a_v4; v += 256) {
        const int c = v / (8 * D);
        const int j = v - c * (8 * D);
        const int b = b_lo + c;
        const float4 q = *(const float4*)(x + (size_t)b * DTOT + OFF + k0 * D + j * 4);
        #pragma unroll
        for (int e = 0; e < 4; ++e) {
            const int tt  = j * 4 + e;
            const int ul  = tt / D;
            const int ii  = tt - ul * D;
            const int rho = b * D + ii - rho0;
            if (rho >= 0 && rho < 128) {
                const float fv = (e == 0) ? q.x : (e == 1) ? q.y : (e == 2) ? q.z : q.w;
                As[rho * 32 + (ul ^ ((rho & 7) << 2))] = __uint_as_float(f2tf32(fv));
            }
        }
    }
}

__device__ __forceinline__ void load_B(const float* __restrict__ wt, uint32_t Bs_u32,
                                       int n0, int k0) {
    #pragma unroll
    for (int r = 0; r < 4; ++r) {
        const int q = threadIdx.x + r * 256;      // 1024 chunks of 16B
        const int n = q >> 3, j = q & 7;
        const float* src = wt + (size_t)(n0 + n) * MULC + k0 + j * 4;
        const uint32_t c0 = (uint32_t)((4 * j) ^ ((n & 7) << 2));
        cp_async16(Bs_u32 + (uint32_t)(n * 32 + c0) * 4, src);
    }
}

// ---------------- per-tile body ----------------
template <int D, int OFF>
__device__ __forceinline__ void tile_body(
    const float* __restrict__ x, const float* __restrict__ bias0,
    float* __restrict__ out, char* sm, uint32_t sm32, int rho0, int n0)
{
    const int tid  = threadIdx.x;
    const int lane = tid & 31, wid = tid >> 5;
    const int g = lane >> 2, t4 = lane & 3;
    const int wm = wid >> 2, wn = wid & 3;      // 2 x 4 warp grid
    const float* wt = g_Wt + ((D == 1) ? 0 : (D == 3) ? 1 : 2) * MULC * MULC;

    const int b_lo = rho0 / D;
    const int b_hi = (rho0 + 127) / D;
    const int nb   = b_hi - b_lo + 1;

    float acc[4][4][4];
    #pragma unroll
    for (int mt = 0; mt < 4; ++mt)
        #pragma unroll
        for (int nt = 0; nt < 4; ++nt)
            #pragma unroll
            for (int e = 0; e < 4; ++e) acc[mt][nt][e] = 0.0f;

    // prologue: stage 0
    load_A<D, OFF>(x, (float*)sm, rho0, 0, b_lo, nb);
    load_B(wt, sm32 + BS_OFF, n0, 0);
    cp_commit();

    for (int kc = 0; kc < 16; ++kc) {
        const uint32_t cur = (kc & 1) * STAGE_BYTES;
        if (kc < 15) {
            const uint32_t nxt = ((kc + 1) & 1) * STAGE_BYTES;
            load_A<D, OFF>(x, (float*)(sm + nxt), rho0, (kc + 1) * 32, b_lo, nb);
            load_B(wt, sm32 + nxt + BS_OFF, n0, (kc + 1) * 32);
            cp_commit();
            cp_wait<1>();
        } else {
            cp_wait<0>();
        }
        __syncthreads();

        const float* As = (const float*)(sm + cur);
        const float* Bs = (const float*)(sm + cur + BS_OFF);

        #pragma unroll
        for (int ks = 0; ks < 4; ++ks) {
            const int kb = ks * 8;
            uint32_t af[4][4];
            #pragma unroll
            for (int mt = 0; mt < 4; ++mt) {
                const int r0 = wm * 64 + mt * 16 + g, r1 = r0 + 8;
                const int c0 = kb + t4, c1 = c0 + 4;
                af[mt][0] = __float_as_uint(As[r0 * 32 + (c0 ^ ((r0 & 7) << 2))]);
                af[mt][1] = __float_as_uint(As[r1 * 32 + (c0 ^ ((r1 & 7) << 2))]);
                af[mt][2] = __float_as_uint(As[r0 * 32 + (c1 ^ ((r0 & 7) << 2))]);
                af[mt][3] = __float_as_uint(As[r1 * 32 + (c1 ^ ((r1 & 7) << 2))]);
            }
            uint32_t bf[4][2];
            #pragma unroll
            for (int nt = 0; nt < 4; ++nt) {
                const int n = wn * 32 + nt * 8 + g;
                const int c0 = kb + t4, c1 = c0 + 4;
                bf[nt][0] = __float_as_uint(Bs[n * 32 + (c0 ^ ((n & 7) << 2))]);
                bf[nt][1] = __float_as_uint(Bs[n * 32 + (c1 ^ ((n & 7) << 2))]);
            }
            #pragma unroll
            for (int mt = 0; mt < 4; ++mt)
                #pragma unroll
                for (int nt = 0; nt < 4; ++nt)
                    mma_tf32(acc[mt][nt], af[mt], bf[nt]);
        }
        __syncthreads();   // protect buffer about to be overwritten next iter
    }

    // ---- epilogue: C regs -> padded smem -> coalesced deinterleaved STG ----
    float* Cs = (float*)sm;
    #pragma unroll
    for (int mt = 0; mt < 4; ++mt) {
        const int r0 = wm * 64 + mt * 16 + g, r1 = r0 + 8;
        #pragma unroll
        for (int nt = 0; nt < 4; ++nt) {
            const int cc = wn * 32 + nt * 8 + t4 * 2;
            Cs[r0 * CS_PITCH + cc]     = acc[mt][nt][0];
            Cs[r0 * CS_PITCH + cc + 1] = acc[mt][nt][1];
            Cs[r1 * CS_PITCH + cc]     = acc[mt][nt][2];
            Cs[r1 * CS_PITCH + cc + 1] = acc[mt][nt][3];
        }
    }
    __syncthreads();

    const int chunk = 128 * D;
    const int total = nb * chunk;
    for (int idx = tid; idx < total; idx += 256) {
        const int bc = idx / chunk;
        const int p  = idx - bc * chunk;
        const int b  = b_lo + bc;
        const int wl = p / D;
        const int ii = p - wl * D;
        const int rho = b * D + ii - rho0;
        if (rho >= 0 && rho < 128) {
            float v = Cs[rho * CS_PITCH + wl];
            if (D == 1) v += bias0[n0 + wl];
            out[(size_t)b * DTOT + OFF + n0 * D + p] = v;
        }
    }
}

// ---------------- main kernel ----------------
__global__ void __launch_bounds__(256)
gemm_kernel(const float* __restrict__ x, const float* __restrict__ b0,
            float* __restrict__ out) {
    extern __shared__ char sm[];
    const uint32_t sm32 = smem_u32(sm);

    const int t = blockIdx.x;
    const int mt = t >> 2;
    const int n0 = (t & 3) * 128;

    if (mt < 32)        tile_body<1, 0>   (x, b0, out, sm, sm32, mt * 128,         n0);
    else if (mt < 128)  tile_body<3, 512> (x, b0, out, sm, sm32, (mt - 32) * 128,  n0);
    else                tile_body<5, 2048>(x, b0, out, sm, sm32, (mt - 128) * 128, n0);
}

// ---------------- launch ----------------
extern "C" void kernel_launch(void* const* d_in, const int* in_sizes, int n_in,
                              void* d_out, int out_size) {
    (void)in_sizes; (void)n_in; (void)out_size;
    const float* x  = (const float*)d_in[0];
    const float* w0 = (const float*)d_in[1];
    const float* w1 = (const float*)d_in[2];
    const float* w2 = (const float*)d_in[3];
    const float* b0 = (const float*)d_in[4];
    float* out = (float*)d_out;

    cudaFuncSetAttribute(gemm_kernel, cudaFuncAttributeMaxDynamicSharedMemorySize,
                         (int)SMEM_BYTES);

    dim3 pg(16, 16, 3), pb(32, 8);
    prep_w_kernel<<<pg, pb>>>(w0, w1, w2);

    gemm_kernel<<<1152, 256, SMEM_BYTES>>>(x, b0, out);
}

// round 3
// speedup vs baseline: 1.5789x; 1.5789x over previous
#include <cuda_runtime.h>
#include <cstdint>

// ============================================================================
// FlaxLinear per-irrep (mul=512, irreps 0e+1e+2e) fused GEMM for sm_103 (base
// PTX target -> legacy mma.sync tf32; no tcgen05 available in this pipeline).
//
// R3 structure:
//   prep_w : Wt[l][w][u] = rna_tf32(PW * w_l[u][w])          (K-major B)
//   prep_x : Xt[rho][u]  = rna_tf32(x[b, off+u*D+i])         (K-major A,
//            rho-major; deinterleave paid ONCE, bandwidth-bound)
//   gemm   : 128x128 CTA tile, K=512 in 16 chunks of 32, 3-stage cp.async
//            pipeline, ldmatrix.x4 fragment loads, m16n8k8 tf32 MMA.
//   epilogue: C regs -> padded smem -> coalesced deinterleaved stores (+bias).
// ============================================================================

#define MULC 512
#define DTOT 4608
#define PW   0.044194173824159216f   // 512^-0.5

// rows: l0 [0,4096), l1 [4096,16384), l2 [16384,36864)
#define RTOT 36864

__device__ float g_Wt[3 * MULC * MULC];
__device__ float g_Xt[RTOT * MULC];

// ---------------- helpers ----------------
__device__ __forceinline__ uint32_t smem_u32(const void* p) {
    uint32_t a;
    asm("{ .reg .u64 t; cvta.to.shared.u64 t, %1; cvt.u32.u64 %0, t; }" : "=r"(a) : "l"(p));
    return a;
}
__device__ __forceinline__ uint32_t f2tf32(float f) {
    uint32_t u; asm("cvt.rna.tf32.f32 %0, %1;" : "=r"(u) : "f"(f)); return u;
}
__device__ __forceinline__ void mma_tf32(float* c, const uint32_t* a, const uint32_t* b) {
    asm volatile(
        "mma.sync.aligned.m16n8k8.row.col.f32.tf32.tf32.f32 "
        "{%0,%1,%2,%3},{%4,%5,%6,%7},{%8,%9},{%0,%1,%2,%3};"
        : "+f"(c[0]), "+f"(c[1]), "+f"(c[2]), "+f"(c[3])
        : "r"(a[0]), "r"(a[1]), "r"(a[2]), "r"(a[3]), "r"(b[0]), "r"(b[1]));
}
__device__ __forceinline__ void ldsm_x4(uint32_t* r, uint32_t addr) {
    asm volatile("ldmatrix.sync.aligned.m8n8.x4.shared.b16 {%0,%1,%2,%3}, [%4];"
                 : "=r"(r[0]), "=r"(r[1]), "=r"(r[2]), "=r"(r[3]) : "r"(addr));
}
__device__ __forceinline__ void cp_async16(uint32_t dst, const void* src) {
    asm volatile("cp.async.cg.shared.global [%0], [%1], 16;" :: "r"(dst), "l"(src) : "memory");
}
__device__ __forceinline__ void cp_commit() {
    asm volatile("cp.async.commit_group;" ::: "memory");
}
template <int N>
__device__ __forceinline__ void cp_wait() {
    asm volatile("cp.async.wait_group %0;" :: "n"(N) : "memory");
}

// smem: 3 stages of 32KB (A 128x32f swizzled, then B 128x32f swizzled).
// XOR swizzle within a 32-float row: col' = col ^ ((row&7)<<2).
static constexpr uint32_t STAGE_BYTES = 32768;
static constexpr uint32_t BS_OFF      = 16384;
static constexpr uint32_t CS_PITCH    = 132;   // epilogue staging pitch (floats)
static constexpr uint32_t SMEM_BYTES  = 3 * STAGE_BYTES;  // 96KB; Cs (67.6KB) reuses it
static_assert(SMEM_BYTES >= 128 * CS_PITCH * 4, "Cs fits");

// ---------------- prep_w: Wt[l][w][u] = rna_tf32(PW * w[u][w]) ----------
__global__ void prep_w_kernel(const float* __restrict__ w0,
                              const float* __restrict__ w1,
                              const float* __restrict__ w2) {
    __shared__ float tile[32][33];
    const int l = blockIdx.z;
    const float* w = (l == 0) ? w0 : (l == 1) ? w1 : w2;
    float* wt = g_Wt + l * MULC * MULC;
    const int u0 = blockIdx.y * 32, c0 = blockIdx.x * 32;
    const int tx = threadIdx.x, ty = threadIdx.y;
    #pragma unroll
    for (int j = ty; j < 32; j += 8)
        tile[j][tx] = w[(u0 + j) * MULC + c0 + tx];
    __syncthreads();
    #pragma unroll
    for (int j = ty; j < 32; j += 8) {
        float v = PW * tile[tx][j];
        wt[(c0 + j) * MULC + u0 + tx] = __uint_as_float(f2tf32(v));
    }
}

// ---------------- prep_x: Xt[BASE + b*D + i][u] = tf32(x[b, OFF + u*D + i]) --
template <int D, int OFF, int BASE>
__global__ void __launch_bounds__(256)
prep_x_kernel(const float* __restrict__ x) {
    __shared__ float s[MULC * D];
    const int b = blockIdx.x;
    const float* row = x + (size_t)b * DTOT + OFF;
    for (int t = threadIdx.x; t < MULC * D; t += 256)
        s[t] = row[t];
    __syncthreads();
    float* dst = g_Xt + (size_t)(BASE + b * D) * MULC;
    for (int t = threadIdx.x; t < MULC * D; t += 256) {
        const int u = t & (MULC - 1);
        const int i = t >> 9;
        dst[(size_t)i * MULC + u] = __uint_as_float(f2tf32(s[u * D + i]));
    }
}

// ---------------- cp.async tile loader: 128 rows x 32 floats, pitch 512 -----
__device__ __forceinline__ void load_tile(const float* __restrict__ src,
                                          uint32_t dst, int k0) {
    #pragma unroll
    for (int r = 0; r < 4; ++r) {
        const int idx = threadIdx.x + r * 256;   // 1024 x 16B
        const int row = idx >> 3, j = idx & 7;
        const uint32_t c = (uint32_t)((4 * j) ^ ((row & 7) << 2));
        cp_async16(dst + (uint32_t)(row * 32 + c) * 4,
                   src + (size_t)row * MULC + k0 + 4 * j);
    }
}

// ---------------- mainloop (D-independent) ----------------
__device__ __forceinline__ void mainloop(const float* __restrict__ Asrc,
                                         const float* __restrict__ Bsrc,
                                         uint32_t sm32, float acc[4][4][4]) {
    const int lane = threadIdx.x & 31, wid = threadIdx.x >> 5;
    const int wm = wid >> 2, wn = wid & 3;     // 2 x 4 warp grid

    #pragma unroll
    for (int mt = 0; mt < 4; ++mt)
        #pragma unroll
        for (int nt = 0; nt < 4; ++nt)
            #pragma unroll
            for (int e = 0; e < 4; ++e) acc[mt][nt][e] = 0.0f;

    // ldmatrix per-lane base offsets (within a stage) ----------------------
    const int q  = lane >> 3;      // matrix index 0..3
    const int rs = lane & 7;       // row within matrix
    // A(mt, ks): row = wm*64 + mt*16 + (q&1)*8 + rs ; colf = ks*8 + (q>>1)*4
    const int a_row_base = wm * 64 + (q & 1) * 8 + rs;
    const int a_col_half = (q >> 1) * 4;
    // B(pair p, ks): row n = wn*32 + (2p + (q>>1))*8 + rs ; colf = ks*8 + (q&1)*4
    const int b_row_base = wn * 32 + (q >> 1) * 8 + rs;
    const int b_col_half = (q & 1) * 4;
    const uint32_t swz = (uint32_t)(rs << 2);

    // prologue: stages 0,1
    load_tile(Asrc, sm32, 0);
    load_tile(Bsrc, sm32 + BS_OFF, 0);
    cp_commit();
    load_tile(Asrc, sm32 + STAGE_BYTES, 32);
    load_tile(Bsrc, sm32 + STAGE_BYTES + BS_OFF, 32);
    cp_commit();

    uint32_t stage_off[3] = {0, STAGE_BYTES, 2 * STAGE_BYTES};
    int cur = 0;

    for (int kc = 0; kc < 16; ++kc) {
        cp_wait<1>();
        __syncthreads();

        if (kc + 2 < 16) {
            const uint32_t nxt = stage_off[(cur + 2) % 3];
            load_tile(Asrc, sm32 + nxt, (kc + 2) * 32);
            load_tile(Bsrc, sm32 + nxt + BS_OFF, (kc + 2) * 32);
        }
        cp_commit();

        const uint32_t Ab = sm32 + stage_off[cur];
        const uint32_t Bb = sm32 + stage_off[cur] + BS_OFF;

        #pragma unroll
        for (int ks = 0; ks < 4; ++ks) {
            uint32_t af[4][4];
            #pragma unroll
            for (int mt = 0; mt < 4; ++mt) {
                const int r = a_row_base + mt * 16;
                const uint32_t c = (uint32_t)(ks * 8 + a_col_half) ^ swz;
                ldsm_x4(af[mt], Ab + (uint32_t)(r * 32 + c) * 4);
            }
            uint32_t bf[4][2];
            #pragma unroll
            for (int p = 0; p < 2; ++p) {
                const int n = b_row_base + p * 16;
                const uint32_t c = (uint32_t)(ks * 8 + b_col_half) ^ swz;
                ldsm_x4(&bf[2 * p][0], Bb + (uint32_t)(n * 32 + c) * 4);
            }
            #pragma unroll
            for (int mt = 0; mt < 4; ++mt)
                #pragma unroll
                for (int nt = 0; nt < 4; ++nt)
                    mma_tf32(acc[mt][nt], af[mt], bf[nt]);
        }
        cur = (cur + 1) % 3;
    }
}

// ---------------- epilogue (D-templated, layout validated in R2) ------------
template <int D, int OFF>
__device__ __forceinline__ void epilogue(float acc[4][4][4],
                                         const float* __restrict__ bias0,
                                         float* __restrict__ out, char* sm,
                                         int rho0, int n0) {
    const int tid  = threadIdx.x;
    const int lane = tid & 31, wid = tid >> 5;
    const int g = lane >> 2, t4 = lane & 3;
    const int wm = wid >> 2, wn = wid & 3;

    __syncthreads();   // mainloop stage buffers are dead after this
    float* Cs = (float*)sm;
    #pragma unroll
    for (int mt = 0; mt < 4; ++mt) {
        const int r0 = wm * 64 + mt * 16 + g, r1 = r0 + 8;
        #pragma unroll
        for (int nt = 0; nt < 4; ++nt) {
            const int cc = wn * 32 + nt * 8 + t4 * 2;
            Cs[r0 * CS_PITCH + cc]     = acc[mt][nt][0];
            Cs[r0 * CS_PITCH + cc + 1] = acc[mt][nt][1];
            Cs[r1 * CS_PITCH + cc]     = acc[mt][nt][2];
            Cs[r1 * CS_PITCH + cc + 1] = acc[mt][nt][3];
        }
    }
    __syncthreads();

    const int b_lo = rho0 / D;
    const int b_hi = (rho0 + 127) / D;
    const int nb   = b_hi - b_lo + 1;
    const int chunk = 128 * D;
    const int total = nb * chunk;
    for (int idx = tid; idx < total; idx += 256) {
        const int bc = idx / chunk;
        const int p  = idx - bc * chunk;
        const int b  = b_lo + bc;
        const int wl = p / D;
        const int ii = p - wl * D;
        const int rho = b * D + ii - rho0;
        if (rho >= 0 && rho < 128) {
            float v = Cs[rho * CS_PITCH + wl];
            if (D == 1) v += bias0[n0 + wl];
            out[(size_t)b * DTOT + OFF + n0 * D + p] = v;
        }
    }
}

// ---------------- main kernel ----------------
__global__ void __launch_bounds__(256, 2)
gemm_kernel(const float* __restrict__ b0, float* __restrict__ out) {
    extern __shared__ char sm[];
    const uint32_t sm32 = smem_u32(sm);

    const int tile = blockIdx.x >> 2;
    const int n0   = (blockIdx.x & 3) * 128;

    int l, rho0, base;
    if (tile < 32)       { l = 0; rho0 = tile * 128;         base = 0; }
    else if (tile < 128) { l = 1; rho0 = (tile - 32) * 128;  base = 4096; }
    else                 { l = 2; rho0 = (tile - 128) * 128; base = 16384; }

    const float* Asrc = g_Xt + (size_t)(base + rho0) * MULC;
    const float* Bsrc = g_Wt + (size_t)l * MULC * MULC + (size_t)n0 * MULC;

    float acc[4][4][4];
    mainloop(Asrc, Bsrc, sm32, acc);

    if (l == 0)      epilogue<1, 0>   (acc, b0, out, sm, rho0, n0);
    else if (l == 1) epilogue<3, 512> (acc, b0, out, sm, rho0, n0);
    else             epilogue<5, 2048>(acc, b0, out, sm, rho0, n0);
}

// ---------------- launch ----------------
extern "C" void kernel_launch(void* const* d_in, const int* in_sizes, int n_in,
                              void* d_out, int out_size) {
    (void)in_sizes; (void)n_in; (void)out_size;
    const float* x  = (const float*)d_in[0];
    const float* w0 = (const float*)d_in[1];
    const float* w1 = (const float*)d_in[2];
    const float* w2 = (const float*)d_in[3];
    const float* b0 = (const float*)d_in[4];
    float* out = (float*)d_out;

    cudaFuncSetAttribute(gemm_kernel, cudaFuncAttributeMaxDynamicSharedMemorySize,
                         (int)SMEM_BYTES);

    dim3 pg(16, 16, 3), pb(32, 8);
    prep_w_kernel<<<pg, pb>>>(w0, w1, w2);

    prep_x_kernel<1, 0,    0>    <<<4096, 256>>>(x);
    prep_x_kernel<3, 512,  4096> <<<4096, 256>>>(x);
    prep_x_kernel<5, 2048, 16384><<<4096, 256>>>(x);

    gemm_kernel<<<1152, 256, SMEM_BYTES>>>(b0, out);
}